// round 12
// baseline (speedup 1.0000x reference)
#include <cuda_runtime.h>
#include <cuda_fp16.h>
#include <cstdint>

// ---------------- problem constants ----------------------------------------
#define DMODEL 512
#define NEXP   8
#define NTOK   16384
#define NKROWS 32768          // NTOK * top_k
#define BM     128
#define BN     256            // CTA N tile (512 threads)
#define BKc    32             // fp16 k per chunk
#define NCHUNK (DMODEL / BKc) // 16
#define ASTR   40             // smem row stride in fp16 elems (32 + 8 pad = 80B)
#define STAGES 3
#define A_STAGE_BYTES (BM * ASTR * 2)   // 10240
#define B_STAGE_BYTES (BN * ASTR * 2)   // 20480

#define NBLK_ROUTE (NKROWS / 256)                      // 128
#define NBLK_CONVX (NTOK * DMODEL / 16 / 256)          // 2048 (16 floats/thread)
#define NBLK_CONVW (NEXP * (DMODEL / 32) * (DMODEL / 32))  // 2048

// ---------------- static device scratch -------------------------------------
__device__ int   g_blkcnt[NBLK_ROUTE * NEXP];
__device__ int   g_off[NEXP + 1];
__device__ int   g_tok[NKROWS];                    // compact pos -> token id
__device__ float g_prb[NKROWS];                    // compact pos -> gate prob
__device__ __half g_xf[NTOK * DMODEL];
__device__ __half g_Bt[NEXP * DMODEL * DMODEL];

// ---------------- helpers ----------------------------------------------------
__device__ __forceinline__ uint32_t smem_u32(const void* p) {
    uint32_t a;
    asm("{ .reg .u64 t; cvta.to.shared.u64 t, %1; cvt.u32.u64 %0, t; }"
        : "=r"(a) : "l"(p));
    return a;
}
__device__ __forceinline__ void cp16(uint32_t dst, const void* src) {
    asm volatile("cp.async.ca.shared.global [%0], [%1], 16;"
                 :: "r"(dst), "l"(src) : "memory");
}
#define CP_COMMIT() asm volatile("cp.async.commit_group;" ::: "memory")
#define CP_WAIT1()  asm volatile("cp.async.wait_group 1;" ::: "memory")
#define CP_WAIT0()  asm volatile("cp.async.wait_group 0;" ::: "memory")

__device__ __forceinline__ void ldsm_x4(uint32_t* r, uint32_t addr) {
    asm volatile("ldmatrix.sync.aligned.m8n8.x4.shared.b16 {%0,%1,%2,%3}, [%4];"
                 : "=r"(r[0]), "=r"(r[1]), "=r"(r[2]), "=r"(r[3]) : "r"(addr));
}
__device__ __forceinline__ void mma16816(float* c, const uint32_t* a,
                                         uint32_t b0, uint32_t b1) {
    asm volatile(
        "mma.sync.aligned.m16n8k16.row.col.f32.f16.f16.f32 "
        "{%0,%1,%2,%3}, {%4,%5,%6,%7}, {%8,%9}, {%0,%1,%2,%3};"
        : "+f"(c[0]), "+f"(c[1]), "+f"(c[2]), "+f"(c[3])
        : "r"(a[0]), "r"(a[1]), "r"(a[2]), "r"(a[3]), "r"(b0), "r"(b1));
}
__device__ __forceinline__ void redg_v2_f32(float* p, float v0, float v1) {
    asm volatile("red.global.add.v2.f32 [%0], {%1, %2};"
                 :: "l"(p), "f"(v0), "f"(v1) : "memory");
}

// ---------------- K1: histograms + x convert + output zero -------------------
__global__ void k1_count_convx_zero(const int* __restrict__ idx,
                                    const float* __restrict__ x,
                                    float* __restrict__ out, int out_size) {
    const int b = blockIdx.x;
    const int t = threadIdx.x;
    if (b < NBLK_ROUTE) {
        __shared__ int sc[NEXP];
        if (t < NEXP) sc[t] = 0;
        __syncthreads();
        atomicAdd(&sc[idx[b * 256 + t]], 1);
        __syncthreads();
        if (t < NEXP) g_blkcnt[b * NEXP + t] = sc[t];
    } else if (b < NBLK_ROUTE + NBLK_CONVX) {
        // 16 floats per thread: two independent 16B loads in flight
        int i = (b - NBLK_ROUTE) * 256 + t;
        const float4* src = (const float4*)x + 4 * (size_t)i;
        float4 v0 = src[0];
        float4 v1 = src[1];
        float4 v2 = src[2];
        float4 v3 = src[3];
        __half2* dst = (__half2*)(g_xf + 16 * (size_t)i);
        dst[0] = __floats2half2_rn(v0.x, v0.y);
        dst[1] = __floats2half2_rn(v0.z, v0.w);
        dst[2] = __floats2half2_rn(v1.x, v1.y);
        dst[3] = __floats2half2_rn(v1.z, v1.w);
        dst[4] = __floats2half2_rn(v2.x, v2.y);
        dst[5] = __floats2half2_rn(v2.z, v2.w);
        dst[6] = __floats2half2_rn(v3.x, v3.y);
        dst[7] = __floats2half2_rn(v3.z, v3.w);
    } else {
        // zero the output buffer (accumulation target + loss tail)
        int j = (b - NBLK_ROUTE - NBLK_CONVX) * 256 + t;   // per 4 floats
        int base = 4 * j;
        if (base + 3 < out_size) {
            ((float4*)out)[j] = make_float4(0.f, 0.f, 0.f, 0.f);
        } else if (base < out_size) {
            for (int q = base; q < out_size; q++) out[q] = 0.0f;
        }
    }
}

// ---------------- K2: place tokens + W transpose/convert ---------------------
__global__ void k2_place_convw(const int* __restrict__ idx,
                               const float* __restrict__ prob,
                               const float* __restrict__ W) {
    const int b = blockIdx.x;
    const int t = threadIdx.x;
    if (b < NBLK_ROUTE) {
        __shared__ int cnt[NBLK_ROUTE * NEXP];   // 4 KB
        __shared__ int stot[NEXP], sbase[NEXP], soff[NEXP + 1], scur[NEXP];
        for (int j = t; j < NBLK_ROUTE * NEXP; j += 256) cnt[j] = g_blkcnt[j];
        if (t < NEXP) scur[t] = 0;
        __syncthreads();
        if (t < NEXP) {
            int tot = 0, bb = 0;
            for (int blk = 0; blk < NBLK_ROUTE; blk++) {
                int c = cnt[blk * NEXP + t];
                if (blk < b) bb += c;
                tot += c;
            }
            stot[t] = tot;
            sbase[t] = bb;
        }
        __syncthreads();
        if (t == 0) {
            int acc = 0;
            for (int e2 = 0; e2 < NEXP; e2++) { soff[e2] = acc; acc += stot[e2]; }
            soff[NEXP] = acc;
        }
        __syncthreads();
        int i = b * 256 + t;
        int e = idx[i];
        int lp = atomicAdd(&scur[e], 1);
        int pos = soff[e] + sbase[e] + lp;
        g_tok[pos] = i >> 1;
        g_prb[pos] = prob[i];
        if (b == 0 && t <= NEXP) g_off[t] = soff[t];
    } else {
        __shared__ float tile[32][33];
        int w = b - NBLK_ROUTE;
        int e = w >> 8;
        int k0 = (w & 15) * 32;
        int n0 = ((w >> 4) & 15) * 32;
        int tx = t & 31, ty = t >> 5;
        const float* Wb = W + (size_t)e * DMODEL * DMODEL;
        for (int r = ty; r < 32; r += 8)
            tile[r][tx] = Wb[(size_t)(k0 + r) * DMODEL + n0 + tx];
        __syncthreads();
        __half* Be = g_Bt + (size_t)e * DMODEL * DMODEL;
        for (int r = ty; r < 32; r += 8)
            Be[(size_t)(n0 + r) * DMODEL + k0 + tx] = __float2half_rn(tile[tx][r]);
    }
}

// ---------------- grouped GEMM: 128x256 CTA, v2 atomic fp32 epilogue ---------
__global__ __launch_bounds__(512, 1)
void moe_gemm_kernel(const float* __restrict__ bias, float* __restrict__ out) {
    const int e = blockIdx.z;
    const int r0 = g_off[e], r1 = g_off[e + 1];
    const int m0 = r0 + blockIdx.y * BM;
    if (m0 >= r1) return;
    const int n0 = blockIdx.x * BN;

    extern __shared__ __half dsm[];
    __half* sA = dsm;                                   // [STAGES][BM*ASTR]
    __half* sB = dsm + STAGES * BM * ASTR;              // [STAGES][BN*ASTR]
    __shared__ int   sTok[BM];
    __shared__ float sPrb[BM];

    const int tid  = threadIdx.x;
    const int wid  = tid >> 5;
    const int lane = tid & 31;
    const int wm   = wid & 3;     // 4 M slices of 32 rows
    const int wn   = wid >> 2;    // 4 N slices of 64 cols

    if (tid < BM) {
        int r = m0 + tid;
        sTok[tid] = (r < r1) ? g_tok[r] : g_tok[m0];
        sPrb[tid] = (r < r1) ? g_prb[r] : 0.0f;
    }
    __syncthreads();

    // global-load mapping:
    const int lrA = tid >> 2, lqA = tid & 3;
    const int c0 = tid, c1 = tid + 512;
    const int lrB0 = c0 >> 2, lqB0 = c0 & 3;
    const int lrB1 = c1 >> 2, lqB1 = c1 & 3;

    const __half* Arow  = g_xf + (size_t)sTok[lrA] * DMODEL + lqA * 8;
    const __half* Brow0 = g_Bt + ((size_t)e * DMODEL + n0 + lrB0) * DMODEL + lqB0 * 8;
    const __half* Brow1 = g_Bt + ((size_t)e * DMODEL + n0 + lrB1) * DMODEL + lqB1 * 8;
    const uint32_t sAa  = smem_u32(sA) + (uint32_t)(lrA * 80 + lqA * 16);
    const uint32_t sBa0 = smem_u32(sB) + (uint32_t)(lrB0 * 80 + lqB0 * 16);
    const uint32_t sBa1 = smem_u32(sB) + (uint32_t)(lrB1 * 80 + lqB1 * 16);

    auto load_stage = [&](int t) {
        int buf = t % STAGES;
        int kc = t * BKc;
        cp16(sAa  + buf * A_STAGE_BYTES, Arow  + kc);
        cp16(sBa0 + buf * B_STAGE_BYTES, Brow0 + kc);
        cp16(sBa1 + buf * B_STAGE_BYTES, Brow1 + kc);
        CP_COMMIT();
    };

    float acc[2][8][4];
#pragma unroll
    for (int i = 0; i < 2; i++)
#pragma unroll
        for (int j = 0; j < 8; j++)
#pragma unroll
            for (int q = 0; q < 4; q++) acc[i][j][q] = 0.0f;

    // ldmatrix lane addressing
    const int aRow = wm * 32 + (lane & 7) + ((lane >> 3) & 1) * 8;
    const int aK   = ((lane >> 4) & 1) * 8;
    const int bRow = wn * 64 + (lane & 7) + ((lane >> 4) & 1) * 8;
    const int bK   = ((lane >> 3) & 1) * 8;
    const uint32_t aLd = smem_u32(sA) + (uint32_t)(aRow * 80 + aK * 2);
    const uint32_t bLd = smem_u32(sB) + (uint32_t)(bRow * 80 + bK * 2);

    load_stage(0);
    load_stage(1);

    for (int t = 0; t < NCHUNK; t++) {
        const int buf = t % STAGES;
        if (t < NCHUNK - 1) { CP_WAIT1(); } else { CP_WAIT0(); }
        __syncthreads();
        if (t + 2 < NCHUNK) load_stage(t + 2);

        const uint32_t aBase = aLd + buf * A_STAGE_BYTES;
        const uint32_t bBase = bLd + buf * B_STAGE_BYTES;
#pragma unroll
        for (int k16 = 0; k16 < 2; k16++) {
            uint32_t a[2][4];
#pragma unroll
            for (int mt = 0; mt < 2; mt++)
                ldsm_x4(a[mt], aBase + mt * 16 * 80 + k16 * 32);
            uint32_t b[4][4];
#pragma unroll
            for (int nt2 = 0; nt2 < 4; nt2++)
                ldsm_x4(b[nt2], bBase + nt2 * 16 * 80 + k16 * 32);
#pragma unroll
            for (int mt = 0; mt < 2; mt++)
#pragma unroll
                for (int nt2 = 0; nt2 < 4; nt2++) {
                    mma16816(acc[mt][2 * nt2 + 0], a[mt], b[nt2][0], b[nt2][1]);
                    mma16816(acc[mt][2 * nt2 + 1], a[mt], b[nt2][2], b[nt2][3]);
                }
        }
    }

    // ---- epilogue: out[tok] += p * (acc + bias) via red.v2.f32 ----
    // Each output element gets exactly 2 contributions (top-k = 2, distinct
    // experts); IEEE add is commutative, so the result is bit-deterministic.
    const int qrow = lane >> 2;
    const int qcol = 2 * (lane & 3);
    const float* bcol = bias + (size_t)e * DMODEL + n0 + wn * 64 + qcol;
    float2 bv[8];
#pragma unroll
    for (int nt = 0; nt < 8; nt++) bv[nt] = *(const float2*)(bcol + nt * 8);

#pragma unroll
    for (int mt = 0; mt < 2; mt++) {
        int lbase = wm * 32 + mt * 16 + qrow;
#pragma unroll
        for (int half = 0; half < 2; half++) {
            int lrow = lbase + half * 8;
            if (m0 + lrow < r1) {
                float p = sPrb[lrow];
                float* orow = out + (size_t)sTok[lrow] * DMODEL + n0 + wn * 64 + qcol;
#pragma unroll
                for (int nt = 0; nt < 8; nt++) {
                    redg_v2_f32(orow + nt * 8,
                                p * (acc[mt][nt][2 * half]     + bv[nt].x),
                                p * (acc[mt][nt][2 * half + 1] + bv[nt].y));
                }
            }
        }
    }
}

// ---------------- launch -----------------------------------------------------
extern "C" void kernel_launch(void* const* d_in, const int* in_sizes, int n_in,
                              void* d_out, int out_size) {
    const float* x    = (const float*)d_in[0];
    const float* prob = (const float*)d_in[1];
    const int*   idx  = (const int*)d_in[2];
    const float* W    = (const float*)d_in[3];
    const float* bias = (const float*)d_in[4];

    static int smem_set = 0;
    const int SMEMB = STAGES * (A_STAGE_BYTES + B_STAGE_BYTES);  // 92160
    if (!smem_set) {
        cudaFuncSetAttribute(moe_gemm_kernel,
                             cudaFuncAttributeMaxDynamicSharedMemorySize, SMEMB);
        smem_set = 1;
    }

    int zero_blocks = ((out_size + 3) / 4 + 255) / 256;
    k1_count_convx_zero<<<NBLK_ROUTE + NBLK_CONVX + zero_blocks, 256>>>(
        idx, x, (float*)d_out, out_size);
    k2_place_convw<<<NBLK_ROUTE + NBLK_CONVW, 256>>>(idx, prob, W);

    dim3 ggrid(DMODEL / BN, NKROWS / BM, NEXP);   // (2, 256, 8)
    moe_gemm_kernel<<<ggrid, 512, SMEMB>>>(bias, (float*)d_out);
}

// round 13
// speedup vs baseline: 1.1105x; 1.1105x over previous
#include <cuda_runtime.h>
#include <cuda_fp16.h>
#include <cstdint>

// ---------------- problem constants ----------------------------------------
#define DMODEL 512
#define NEXP   8
#define NTOK   16384
#define NKROWS 32768          // NTOK * top_k
#define BM     128
#define BN     256            // CTA N tile (512 threads)
#define BKc    32             // fp16 k per chunk
#define NCHUNK (DMODEL / BKc) // 16
#define ASTR   40             // smem row stride in fp16 elems (32 + 8 pad = 80B)
#define STAGES 3
#define A_STAGE_BYTES (BM * ASTR * 2)   // 10240
#define B_STAGE_BYTES (BN * ASTR * 2)   // 20480

#define NBLK_ROUTE (NKROWS / 256)                      // 128
#define NBLK_CONVX (NTOK * DMODEL / 4 / 1024)          // 2048 blocks, 1024 f4 each
#define NBLK_CONVW (NEXP * (DMODEL / 32) * (DMODEL / 32))  // 2048

// ---------------- static device scratch -------------------------------------
__device__ int   g_blkcnt[NBLK_ROUTE * NEXP];
__device__ int   g_off[NEXP + 1];
__device__ int   g_tok[NKROWS];                    // compact pos -> token id
__device__ float g_prb[NKROWS];                    // compact pos -> gate prob
__device__ __half g_xf[NTOK * DMODEL];
__device__ __half g_Bt[NEXP * DMODEL * DMODEL];

// ---------------- helpers ----------------------------------------------------
__device__ __forceinline__ uint32_t smem_u32(const void* p) {
    uint32_t a;
    asm("{ .reg .u64 t; cvta.to.shared.u64 t, %1; cvt.u32.u64 %0, t; }"
        : "=r"(a) : "l"(p));
    return a;
}
__device__ __forceinline__ void cp16(uint32_t dst, const void* src) {
    asm volatile("cp.async.ca.shared.global [%0], [%1], 16;"
                 :: "r"(dst), "l"(src) : "memory");
}
#define CP_COMMIT() asm volatile("cp.async.commit_group;" ::: "memory")
#define CP_WAIT1()  asm volatile("cp.async.wait_group 1;" ::: "memory")
#define CP_WAIT0()  asm volatile("cp.async.wait_group 0;" ::: "memory")

__device__ __forceinline__ void ldsm_x4(uint32_t* r, uint32_t addr) {
    asm volatile("ldmatrix.sync.aligned.m8n8.x4.shared.b16 {%0,%1,%2,%3}, [%4];"
                 : "=r"(r[0]), "=r"(r[1]), "=r"(r[2]), "=r"(r[3]) : "r"(addr));
}
__device__ __forceinline__ void mma16816(float* c, const uint32_t* a,
                                         uint32_t b0, uint32_t b1) {
    asm volatile(
        "mma.sync.aligned.m16n8k16.row.col.f32.f16.f16.f32 "
        "{%0,%1,%2,%3}, {%4,%5,%6,%7}, {%8,%9}, {%0,%1,%2,%3};"
        : "+f"(c[0]), "+f"(c[1]), "+f"(c[2]), "+f"(c[3])
        : "r"(a[0]), "r"(a[1]), "r"(a[2]), "r"(a[3]), "r"(b0), "r"(b1));
}
__device__ __forceinline__ void redg_v2_f32(float* p, float v0, float v1) {
    asm volatile("red.global.add.v2.f32 [%0], {%1, %2};"
                 :: "l"(p), "f"(v0), "f"(v1) : "memory");
}

// ---------------- K1: histograms + x convert + output zero -------------------
// convx: block-strided phases -> every warp request is 4 consecutive lines.
__global__ void k1_count_convx_zero(const int* __restrict__ idx,
                                    const float* __restrict__ x,
                                    float* __restrict__ out, int out_size) {
    const int b = blockIdx.x;
    const int t = threadIdx.x;
    if (b < NBLK_ROUTE) {
        __shared__ int sc[NEXP];
        if (t < NEXP) sc[t] = 0;
        __syncthreads();
        atomicAdd(&sc[idx[b * 256 + t]], 1);
        __syncthreads();
        if (t < NEXP) g_blkcnt[b * NEXP + t] = sc[t];
    } else if (b < NBLK_ROUTE + NBLK_CONVX) {
        // block covers 1024 float4 (4096 floats); 4 coalesced phases
        const size_t base = (size_t)(b - NBLK_ROUTE) * 1024;
        const float4* src = (const float4*)x + base;
        float4 v[4];
#pragma unroll
        for (int ph = 0; ph < 4; ph++) v[ph] = src[ph * 256 + t];
        uint2* dst = (uint2*)g_xf + base;   // one uint2 = 4 halves = 1 float4
#pragma unroll
        for (int ph = 0; ph < 4; ph++) {
            __half2 h0 = __floats2half2_rn(v[ph].x, v[ph].y);
            __half2 h1 = __floats2half2_rn(v[ph].z, v[ph].w);
            uint2 u;
            u.x = *(uint32_t*)&h0;
            u.y = *(uint32_t*)&h1;
            dst[ph * 256 + t] = u;
        }
    } else {
        // zero the output buffer: 4 coalesced float4 phases per block
        const int zb = b - NBLK_ROUTE - NBLK_CONVX;
        const size_t base = (size_t)zb * 1024;
        const float4 z = make_float4(0.f, 0.f, 0.f, 0.f);
#pragma unroll
        for (int ph = 0; ph < 4; ph++) {
            size_t j = base + ph * 256 + t;          // float4 index
            size_t el = 4 * j;
            if (el + 3 < (size_t)out_size) {
                ((float4*)out)[j] = z;
            } else if (el < (size_t)out_size) {
                for (size_t q = el; q < (size_t)out_size; q++) out[q] = 0.0f;
            }
        }
    }
}

// ---------------- K2: place tokens + W transpose/convert ---------------------
__global__ void k2_place_convw(const int* __restrict__ idx,
                               const float* __restrict__ prob,
                               const float* __restrict__ W) {
    const int b = blockIdx.x;
    const int t = threadIdx.x;
    if (b < NBLK_ROUTE) {
        __shared__ int cnt[NBLK_ROUTE * NEXP];   // 4 KB
        __shared__ int stot[NEXP], sbase[NEXP], soff[NEXP + 1], scur[NEXP];
        for (int j = t; j < NBLK_ROUTE * NEXP; j += 256) cnt[j] = g_blkcnt[j];
        if (t < NEXP) scur[t] = 0;
        __syncthreads();
        if (t < NEXP) {
            int tot = 0, bb = 0;
            for (int blk = 0; blk < NBLK_ROUTE; blk++) {
                int c = cnt[blk * NEXP + t];
                if (blk < b) bb += c;
                tot += c;
            }
            stot[t] = tot;
            sbase[t] = bb;
        }
        __syncthreads();
        if (t == 0) {
            int acc = 0;
            for (int e2 = 0; e2 < NEXP; e2++) { soff[e2] = acc; acc += stot[e2]; }
            soff[NEXP] = acc;
        }
        __syncthreads();
        int i = b * 256 + t;
        int e = idx[i];
        int lp = atomicAdd(&scur[e], 1);
        int pos = soff[e] + sbase[e] + lp;
        g_tok[pos] = i >> 1;
        g_prb[pos] = prob[i];
        if (b == 0 && t <= NEXP) g_off[t] = soff[t];
    } else {
        __shared__ float tile[32][33];
        int w = b - NBLK_ROUTE;
        int e = w >> 8;
        int k0 = (w & 15) * 32;
        int n0 = ((w >> 4) & 15) * 32;
        int tx = t & 31, ty = t >> 5;
        const float* Wb = W + (size_t)e * DMODEL * DMODEL;
        for (int r = ty; r < 32; r += 8)
            tile[r][tx] = Wb[(size_t)(k0 + r) * DMODEL + n0 + tx];
        __syncthreads();
        __half* Be = g_Bt + (size_t)e * DMODEL * DMODEL;
        for (int r = ty; r < 32; r += 8)
            Be[(size_t)(n0 + r) * DMODEL + k0 + tx] = __float2half_rn(tile[tx][r]);
    }
}

// ---------------- grouped GEMM: 128x256 CTA, v2 atomic fp32 epilogue ---------
__global__ __launch_bounds__(512, 1)
void moe_gemm_kernel(const float* __restrict__ bias, float* __restrict__ out) {
    const int e = blockIdx.z;
    const int r0 = g_off[e], r1 = g_off[e + 1];
    const int m0 = r0 + blockIdx.y * BM;
    if (m0 >= r1) return;
    const int n0 = blockIdx.x * BN;

    extern __shared__ __half dsm[];
    __half* sA = dsm;                                   // [STAGES][BM*ASTR]
    __half* sB = dsm + STAGES * BM * ASTR;              // [STAGES][BN*ASTR]
    __shared__ int   sTok[BM];
    __shared__ float sPrb[BM];

    const int tid  = threadIdx.x;
    const int wid  = tid >> 5;
    const int lane = tid & 31;
    const int wm   = wid & 3;     // 4 M slices of 32 rows
    const int wn   = wid >> 2;    // 4 N slices of 64 cols

    if (tid < BM) {
        int r = m0 + tid;
        sTok[tid] = (r < r1) ? g_tok[r] : g_tok[m0];
        sPrb[tid] = (r < r1) ? g_prb[r] : 0.0f;
    }
    __syncthreads();

    // global-load mapping:
    const int lrA = tid >> 2, lqA = tid & 3;
    const int c0 = tid, c1 = tid + 512;
    const int lrB0 = c0 >> 2, lqB0 = c0 & 3;
    const int lrB1 = c1 >> 2, lqB1 = c1 & 3;

    const __half* Arow  = g_xf + (size_t)sTok[lrA] * DMODEL + lqA * 8;
    const __half* Brow0 = g_Bt + ((size_t)e * DMODEL + n0 + lrB0) * DMODEL + lqB0 * 8;
    const __half* Brow1 = g_Bt + ((size_t)e * DMODEL + n0 + lrB1) * DMODEL + lqB1 * 8;
    const uint32_t sAa  = smem_u32(sA) + (uint32_t)(lrA * 80 + lqA * 16);
    const uint32_t sBa0 = smem_u32(sB) + (uint32_t)(lrB0 * 80 + lqB0 * 16);
    const uint32_t sBa1 = smem_u32(sB) + (uint32_t)(lrB1 * 80 + lqB1 * 16);

    auto load_stage = [&](int t) {
        int buf = t % STAGES;
        int kc = t * BKc;
        cp16(sAa  + buf * A_STAGE_BYTES, Arow  + kc);
        cp16(sBa0 + buf * B_STAGE_BYTES, Brow0 + kc);
        cp16(sBa1 + buf * B_STAGE_BYTES, Brow1 + kc);
        CP_COMMIT();
    };

    float acc[2][8][4];
#pragma unroll
    for (int i = 0; i < 2; i++)
#pragma unroll
        for (int j = 0; j < 8; j++)
#pragma unroll
            for (int q = 0; q < 4; q++) acc[i][j][q] = 0.0f;

    // ldmatrix lane addressing
    const int aRow = wm * 32 + (lane & 7) + ((lane >> 3) & 1) * 8;
    const int aK   = ((lane >> 4) & 1) * 8;
    const int bRow = wn * 64 + (lane & 7) + ((lane >> 4) & 1) * 8;
    const int bK   = ((lane >> 3) & 1) * 8;
    const uint32_t aLd = smem_u32(sA) + (uint32_t)(aRow * 80 + aK * 2);
    const uint32_t bLd = smem_u32(sB) + (uint32_t)(bRow * 80 + bK * 2);

    load_stage(0);
    load_stage(1);

    for (int t = 0; t < NCHUNK; t++) {
        const int buf = t % STAGES;
        if (t < NCHUNK - 1) { CP_WAIT1(); } else { CP_WAIT0(); }
        __syncthreads();
        if (t + 2 < NCHUNK) load_stage(t + 2);

        const uint32_t aBase = aLd + buf * A_STAGE_BYTES;
        const uint32_t bBase = bLd + buf * B_STAGE_BYTES;
#pragma unroll
        for (int k16 = 0; k16 < 2; k16++) {
            uint32_t a[2][4];
#pragma unroll
            for (int mt = 0; mt < 2; mt++)
                ldsm_x4(a[mt], aBase + mt * 16 * 80 + k16 * 32);
            uint32_t b[4][4];
#pragma unroll
            for (int nt2 = 0; nt2 < 4; nt2++)
                ldsm_x4(b[nt2], bBase + nt2 * 16 * 80 + k16 * 32);
#pragma unroll
            for (int mt = 0; mt < 2; mt++)
#pragma unroll
                for (int nt2 = 0; nt2 < 4; nt2++) {
                    mma16816(acc[mt][2 * nt2 + 0], a[mt], b[nt2][0], b[nt2][1]);
                    mma16816(acc[mt][2 * nt2 + 1], a[mt], b[nt2][2], b[nt2][3]);
                }
        }
    }

    // ---- epilogue: out[tok] += p * (acc + bias) via red.v2.f32 ----
    // Exactly 2 contributions per element (top-k=2, distinct experts);
    // IEEE add commutative -> bit-deterministic.
    const int qrow = lane >> 2;
    const int qcol = 2 * (lane & 3);
    const float* bcol = bias + (size_t)e * DMODEL + n0 + wn * 64 + qcol;
    float2 bv[8];
#pragma unroll
    for (int nt = 0; nt < 8; nt++) bv[nt] = *(const float2*)(bcol + nt * 8);

#pragma unroll
    for (int mt = 0; mt < 2; mt++) {
        int lbase = wm * 32 + mt * 16 + qrow;
#pragma unroll
        for (int half = 0; half < 2; half++) {
            int lrow = lbase + half * 8;
            if (m0 + lrow < r1) {
                float p = sPrb[lrow];
                float* orow = out + (size_t)sTok[lrow] * DMODEL + n0 + wn * 64 + qcol;
#pragma unroll
                for (int nt = 0; nt < 8; nt++) {
                    redg_v2_f32(orow + nt * 8,
                                p * (acc[mt][nt][2 * half]     + bv[nt].x),
                                p * (acc[mt][nt][2 * half + 1] + bv[nt].y));
                }
            }
        }
    }
}

// ---------------- launch -----------------------------------------------------
extern "C" void kernel_launch(void* const* d_in, const int* in_sizes, int n_in,
                              void* d_out, int out_size) {
    const float* x    = (const float*)d_in[0];
    const float* prob = (const float*)d_in[1];
    const int*   idx  = (const int*)d_in[2];
    const float* W    = (const float*)d_in[3];
    const float* bias = (const float*)d_in[4];

    static int smem_set = 0;
    const int SMEMB = STAGES * (A_STAGE_BYTES + B_STAGE_BYTES);  // 92160
    if (!smem_set) {
        cudaFuncSetAttribute(moe_gemm_kernel,
                             cudaFuncAttributeMaxDynamicSharedMemorySize, SMEMB);
        smem_set = 1;
    }

    int zero_blocks = (out_size + 4095) / 4096;   // 1024 f4 per block
    k1_count_convx_zero<<<NBLK_ROUTE + NBLK_CONVX + zero_blocks, 256>>>(
        idx, x, (float*)d_out, out_size);
    k2_place_convw<<<NBLK_ROUTE + NBLK_CONVW, 256>>>(idx, prob, W);

    dim3 ggrid(DMODEL / BN, NKROWS / BM, NEXP);   // (2, 256, 8)
    moe_gemm_kernel<<<ggrid, 512, SMEMB>>>(bias, (float*)d_out);
}